// round 14
// baseline (speedup 1.0000x reference)
#include <cuda_runtime.h>
#include <cuda_bf16.h>
#include <cstdint>

// ---------------------------------------------------------------------------
// DiT Swin Transformer block — bf16 mma.sync everywhere (GEMMs + attention).
// GEMM: 256-thread CTAs, BM=128 BN=128 BK=64, cp.async x3, 2 CTAs/SM,
// smem-staged coalesced epilogue. Attention: warp-per-head mma.sync,
// Q fragments via direct LDG (2 CTAs/SM). adaLN: 4 rows/warp batched loads.
// B=16, H=W=64, L=4096, C=256, COND=128, HID=1024, NH=8, hd=32, WS=8, SHIFT=4
// ---------------------------------------------------------------------------

namespace {
constexpr int kB     = 16;
constexpr int kW     = 64;
constexpr int kL     = 64 * 64;        // 4096
constexpr int kC     = 256;
constexpr int kCond  = 128;
constexpr int kHid   = 1024;
constexpr int kNH    = 8;
constexpr int kN     = 64;             // tokens / window
constexpr int kShift = 4;
constexpr int kM     = kB * kL;        // 65536 rows
constexpr int kNWin  = kM / kN;        // 1024 windows

constexpr int kBM = 128, kBN = 128, kBK = 64;
constexpr int kAStr = kBK + 8;          // 72 bf16 = 144 B rows
constexpr int kBStr = kBN + 8;          // 136 bf16 = 272 B rows
constexpr int kABytes = kBM * kAStr * 2;            // 18432
constexpr int kBBytes = kBK * kBStr * 2;            // 17408
constexpr int kStage  = kABytes + kBBytes;          // 35840
constexpr int kStages = 3;
constexpr int kSmemBytes = kStages * kStage;        // 107520 (also > C-stage)

// attention smem: per-warp K/V [64][40] bf16 + per-head bias table
constexpr int kQRow      = 40;
constexpr int kWarpElems = 2 * 64 * kQRow;                       // 5120 bf16
constexpr int kAttnSmem  = 8 * kWarpElems * 2 + 8 * 226 * 4;     // 89152 B
}

// ------------------------------- scratch -----------------------------------
__device__ float g_mod1[kB * 2 * kC];
__device__ float g_mod2[kB * 2 * kC];
__device__ __align__(16) __nv_bfloat16 g_h  [(size_t)kM * kC];
__device__ __align__(16) __nv_bfloat16 g_qkv[(size_t)kM * 3 * kC];
__device__ __align__(16) __nv_bfloat16 g_ow [(size_t)kM * kC];
__device__ __align__(16) float         g_x2 [(size_t)kM * kC];
__device__ __align__(16) __nv_bfloat16 g_h2 [(size_t)kM * kC];
__device__ __align__(16) __nv_bfloat16 g_hid[(size_t)kM * kHid];
__device__ __align__(16) __nv_bfloat16 g_wb[786432];          // bf16 weights

// ---------------------------- helpers ---------------------------------------
__device__ __forceinline__ uint32_t smem_u32(const void* p) {
    uint32_t a;
    asm("{ .reg .u64 t; cvta.to.shared.u64 t, %1; cvt.u32.u64 %0, t; }"
        : "=r"(a) : "l"(p));
    return a;
}
__device__ __forceinline__ void ldsm_x4(uint32_t& r0, uint32_t& r1,
                                        uint32_t& r2, uint32_t& r3, uint32_t a) {
    asm volatile("ldmatrix.sync.aligned.m8n8.x4.shared.b16 {%0,%1,%2,%3}, [%4];"
                 : "=r"(r0), "=r"(r1), "=r"(r2), "=r"(r3) : "r"(a));
}
__device__ __forceinline__ void ldsm_x4_t(uint32_t& r0, uint32_t& r1,
                                          uint32_t& r2, uint32_t& r3, uint32_t a) {
    asm volatile("ldmatrix.sync.aligned.m8n8.x4.trans.shared.b16 {%0,%1,%2,%3}, [%4];"
                 : "=r"(r0), "=r"(r1), "=r"(r2), "=r"(r3) : "r"(a));
}
__device__ __forceinline__ void mma_bf16(float c[4], uint32_t a0, uint32_t a1,
                                         uint32_t a2, uint32_t a3,
                                         uint32_t b0, uint32_t b1) {
    asm volatile(
        "mma.sync.aligned.m16n8k16.row.col.f32.bf16.bf16.f32 "
        "{%0,%1,%2,%3}, {%4,%5,%6,%7}, {%8,%9}, {%0,%1,%2,%3};"
        : "+f"(c[0]), "+f"(c[1]), "+f"(c[2]), "+f"(c[3])
        : "r"(a0), "r"(a1), "r"(a2), "r"(a3), "r"(b0), "r"(b1));
}
__device__ __forceinline__ uint32_t pack_bf16(float x, float y) {
    __nv_bfloat162 v = __floats2bfloat162_rn(x, y);
    return *(uint32_t*)&v;
}
__device__ __forceinline__ void store2(float* C, size_t off, float a, float b) {
    float2 v = {a, b};
    *(float2*)(C + off) = v;
}
__device__ __forceinline__ void store2(__nv_bfloat16* C, size_t off, float a, float b) {
    *(uint32_t*)(C + off) = pack_bf16(a, b);
}

#define CP16(dst, src) \
    asm volatile("cp.async.cg.shared.global [%0], [%1], 16;" :: "r"(dst), "l"(src))
#define CP_COMMIT() asm volatile("cp.async.commit_group;")
#define CP_WAIT1()  asm volatile("cp.async.wait_group 1;")

// ------------------------- cond modulation GEMM ----------------------------
__global__ void mod_kernel(const float* __restrict__ cond,
                           const float* __restrict__ w1, const float* __restrict__ b1,
                           const float* __restrict__ w2, const float* __restrict__ b2)
{
    int b = blockIdx.x, which = blockIdx.y;
    const float* w  = which ? w2 : w1;
    const float* bb = which ? b2 : b1;
    float* out      = which ? g_mod2 : g_mod1;

    __shared__ float cs[kCond];
    int j = threadIdx.x;
    if (j < kCond) cs[j] = cond[b * kCond + j];
    __syncthreads();

    float s = bb[j];
    #pragma unroll 8
    for (int k = 0; k < kCond; k++) s = fmaf(cs[k], w[k * (2 * kC) + j], s);
    out[b * (2 * kC) + j] = s;
}

// ------------- adaLN: 4 rows per warp, batched loads (MLP=8) ---------------
__global__ void __launch_bounds__(256)
adaln_kernel(const float* __restrict__ x, const float* __restrict__ mod,
             const float* __restrict__ g,  const float* __restrict__ bt,
             __nv_bfloat16* __restrict__ out)
{
    int wid  = threadIdx.x >> 5, lane = threadIdx.x & 31;
    int row0 = blockIdx.x * 32 + wid * 4;
    int c0   = lane * 8;

    float4 v[4][2];
    #pragma unroll
    for (int r = 0; r < 4; r++) {
        const float* xr = x + (size_t)(row0 + r) * kC + c0;
        v[r][0] = *(const float4*)(xr);
        v[r][1] = *(const float4*)(xr + 4);
    }

    #pragma unroll
    for (int r = 0; r < 4; r++) {
        float s = v[r][0].x + v[r][0].y + v[r][0].z + v[r][0].w
                + v[r][1].x + v[r][1].y + v[r][1].z + v[r][1].w;
        #pragma unroll
        for (int o = 16; o > 0; o >>= 1) s += __shfl_xor_sync(0xffffffffu, s, o);
        float mu = s * (1.0f / kC);

        float d[8] = {v[r][0].x - mu, v[r][0].y - mu, v[r][0].z - mu, v[r][0].w - mu,
                      v[r][1].x - mu, v[r][1].y - mu, v[r][1].z - mu, v[r][1].w - mu};
        float vs = 0.f;
        #pragma unroll
        for (int e = 0; e < 8; e++) vs = fmaf(d[e], d[e], vs);
        #pragma unroll
        for (int o = 16; o > 0; o >>= 1) vs += __shfl_xor_sync(0xffffffffu, vs, o);
        float rsig = rsqrtf(vs * (1.0f / kC) + 1e-6f);

        int row = row0 + r;
        const float* mrow = mod + (row >> 12) * (2 * kC);
        uint4 pk;
        uint32_t* pw = (uint32_t*)&pk;
        #pragma unroll
        for (int e2 = 0; e2 < 4; e2++) {
            int c = c0 + 2 * e2;
            float dg0 = mrow[c],     db0 = mrow[kC + c];
            float dg1 = mrow[c + 1], db1 = mrow[kC + c + 1];
            float r0 = (g[c]     * (1.0f + dg0)) * (d[2 * e2]     * rsig) + (bt[c]     + db0);
            float r1 = (g[c + 1] * (1.0f + dg1)) * (d[2 * e2 + 1] * rsig) + (bt[c + 1] + db1);
            pw[e2] = pack_bf16(r0, r1);
        }
        *(uint4*)(out + (size_t)row * kC + c0) = pk;
    }
}

// ------------------- weights fp32 -> bf16 (single launch) -------------------
__global__ void to_bf16_all(const float* __restrict__ s0, const float* __restrict__ s1,
                            const float* __restrict__ s2, const float* __restrict__ s3,
                            __nv_bfloat16* __restrict__ dst)
{
    int i = blockIdx.x * 256 + threadIdx.x;          // 0 .. 786431
    const float* src;
    int off;
    if (i < 196608)      { src = s0; off = 0; }
    else if (i < 262144) { src = s1; off = 196608; }
    else if (i < 524288) { src = s2; off = 262144; }
    else                 { src = s3; off = 524288; }
    dst[i] = __float2bfloat16(src[i - off]);
}

// ----------------------------- row gathers ---------------------------------
template <int GATHER>
__device__ __forceinline__ int gather_row(int r)
{
    if (GATHER == 1) {
        int win = r >> 6, n = r & 63;
        int b = win >> 6, wrem = win & 63;
        int yr = ((wrem >> 3) << 3) + (n >> 3);
        int xr = ((wrem & 7) << 3) + (n & 7);
        int y = (yr + kShift) & 63;
        int x = (xr + kShift) & 63;
        return b * kL + y * kW + x;
    } else if (GATHER == 2) {
        int b = r >> 12, rem = r & 4095;
        int y = rem >> 6, x = rem & 63;
        int yr = (y - kShift) & 63;
        int xr = (x - kShift) & 63;
        int win = b * 64 + ((yr >> 3) << 3) + (xr >> 3);
        int n   = ((yr & 7) << 3) + (xr & 7);
        return win * kN + n;
    }
    return r;
}

// ------- bf16 mma GEMM: 256 threads, BK=64, cp.async x3, 2 CTAs/SM ---------
// Epilogue staged through smem -> fully coalesced 16B global stores.
template <int GATHER, int EPI, typename OutT>
__global__ void __launch_bounds__(256, 2)
gemm_tc(const __nv_bfloat16* __restrict__ A, const __nv_bfloat16* __restrict__ Bw,
        const float* __restrict__ bias, const float* __restrict__ res,
        OutT* __restrict__ C, int K, int N)
{
    extern __shared__ __align__(128) char smem[];

    int tid  = threadIdx.x;
    int wid  = tid >> 5, lane = tid & 31;
    int g    = lane >> 2, t = lane & 3;
    int wm   = wid & 3, wn = wid >> 2;
    int row0 = blockIdx.x * kBM;
    int col0 = blockIdx.y * kBN;

    int a_r = (lane & 15);
    int a_c = (lane >> 4) << 3;
    int b_r = (lane & 7) + ((lane >> 3) & 1) * 8;
    int b_c = (lane >> 4) << 3;

    int arowA[4];
    #pragma unroll
    for (int p = 0; p < 4; p++)
        arowA[p] = gather_row<GATHER>(row0 + ((p * 256 + tid) >> 3));

    float acc[2][8][4];
    #pragma unroll
    for (int mt = 0; mt < 2; mt++)
        #pragma unroll
        for (int nt = 0; nt < 8; nt++)
            #pragma unroll
            for (int e = 0; e < 4; e++) acc[mt][nt][e] = 0.f;

    int niter = K >> 6;

    auto load_stage = [&](int i, int slot) {
        int k0 = i << 6;
        char* As = smem + slot * kStage;
        char* Bs = As + kABytes;
        #pragma unroll
        for (int p = 0; p < 4; p++) {
            int idx = tid + p * 256;
            int r = idx >> 3, ch = idx & 7;
            uint32_t dst = smem_u32(As + r * (kAStr * 2) + ch * 16);
            CP16(dst, A + (size_t)arowA[p] * K + k0 + ch * 8);
        }
        #pragma unroll
        for (int p = 0; p < 4; p++) {
            int idx = tid + p * 256;
            int r = idx >> 4, ch = idx & 15;
            uint32_t dst = smem_u32(Bs + r * (kBStr * 2) + ch * 16);
            CP16(dst, Bw + (size_t)(k0 + r) * N + col0 + ch * 8);
        }
        CP_COMMIT();
    };

    load_stage(0, 0);
    load_stage(1, 1);

    for (int i = 0; i < niter; i++) {
        CP_WAIT1();
        __syncthreads();

        if (i + 2 < niter) load_stage(i + 2, (i + 2) % 3);
        else CP_COMMIT();

        uint32_t aB = smem_u32(smem + (i % 3) * kStage);
        uint32_t bB = aB + kABytes;

        #pragma unroll
        for (int ks = 0; ks < 4; ks++) {
            int k0 = ks * 16;
            uint32_t af[2][4];
            #pragma unroll
            for (int mt = 0; mt < 2; mt++) {
                uint32_t addr = aB + (wm * 32 + mt * 16 + a_r) * (kAStr * 2)
                                   + (k0 + a_c) * 2;
                ldsm_x4(af[mt][0], af[mt][1], af[mt][2], af[mt][3], addr);
            }
            uint32_t bf[8][2];
            #pragma unroll
            for (int n2 = 0; n2 < 4; n2++) {
                uint32_t addr = bB + (k0 + b_r) * (kBStr * 2)
                                   + (wn * 64 + n2 * 16 + b_c) * 2;
                uint32_t r0, r1, r2, r3;
                ldsm_x4_t(r0, r1, r2, r3, addr);
                bf[n2 * 2 + 0][0] = r0; bf[n2 * 2 + 0][1] = r1;
                bf[n2 * 2 + 1][0] = r2; bf[n2 * 2 + 1][1] = r3;
            }
            #pragma unroll
            for (int mt = 0; mt < 2; mt++)
                #pragma unroll
                for (int nt = 0; nt < 8; nt++)
                    mma_bf16(acc[mt][nt], af[mt][0], af[mt][1], af[mt][2], af[mt][3],
                             bf[nt][0], bf[nt][1]);
        }
    }

    // -------------------- staged epilogue (coalesced stores) ----------------
    __syncthreads();                       // mainloop done; stage smem is free

    if constexpr (sizeof(OutT) == 4) {
        constexpr int CS = 132;            // fp32 stage stride (528 B rows)
        float* cs = (float*)smem;
        #pragma unroll
        for (int mt = 0; mt < 2; mt++) {
            int r0 = wm * 32 + mt * 16 + g;
            #pragma unroll
            for (int nt = 0; nt < 8; nt++) {
                int cc = wn * 64 + nt * 8 + t * 2;
                float2 bv = *(const float2*)(bias + col0 + cc);
                float v0 = acc[mt][nt][0] + bv.x;
                float v1 = acc[mt][nt][1] + bv.y;
                float v2 = acc[mt][nt][2] + bv.x;
                float v3 = acc[mt][nt][3] + bv.y;
                if (EPI == 1) {
                    v0 = 0.5f * v0 * (1.0f + erff(v0 * 0.70710678118654752f));
                    v1 = 0.5f * v1 * (1.0f + erff(v1 * 0.70710678118654752f));
                    v2 = 0.5f * v2 * (1.0f + erff(v2 * 0.70710678118654752f));
                    v3 = 0.5f * v3 * (1.0f + erff(v3 * 0.70710678118654752f));
                }
                float2 o0 = {v0, v1}, o1 = {v2, v3};
                *(float2*)(cs + r0 * CS + cc)       = o0;
                *(float2*)(cs + (r0 + 8) * CS + cc) = o1;
            }
        }
        __syncthreads();
        #pragma unroll
        for (int it = 0; it < 16; it++) {            // 128 rows x 32 float4
            int idx = it * 256 + tid;
            int r = idx >> 5, ch = idx & 31;
            float4 v = *(float4*)(cs + r * CS + ch * 4);
            size_t go = (size_t)(row0 + r) * N + col0 + ch * 4;
            if (EPI == 2) {
                float4 q = *(const float4*)(res + go);
                v.x += q.x; v.y += q.y; v.z += q.z; v.w += q.w;
            }
            *(float4*)((float*)C + go) = v;
        }
    } else {
        constexpr int CS = 136;            // bf16 stage stride (272 B rows)
        __nv_bfloat16* hs = (__nv_bfloat16*)smem;
        #pragma unroll
        for (int mt = 0; mt < 2; mt++) {
            int r0 = wm * 32 + mt * 16 + g;
            #pragma unroll
            for (int nt = 0; nt < 8; nt++) {
                int cc = wn * 64 + nt * 8 + t * 2;
                float2 bv = *(const float2*)(bias + col0 + cc);
                float v0 = acc[mt][nt][0] + bv.x;
                float v1 = acc[mt][nt][1] + bv.y;
                float v2 = acc[mt][nt][2] + bv.x;
                float v3 = acc[mt][nt][3] + bv.y;
                if (EPI == 1) {
                    v0 = 0.5f * v0 * (1.0f + erff(v0 * 0.70710678118654752f));
                    v1 = 0.5f * v1 * (1.0f + erff(v1 * 0.70710678118654752f));
                    v2 = 0.5f * v2 * (1.0f + erff(v2 * 0.70710678118654752f));
                    v3 = 0.5f * v3 * (1.0f + erff(v3 * 0.70710678118654752f));
                }
                *(uint32_t*)(hs + r0 * CS + cc)       = pack_bf16(v0, v1);
                *(uint32_t*)(hs + (r0 + 8) * CS + cc) = pack_bf16(v2, v3);
            }
        }
        __syncthreads();
        #pragma unroll
        for (int it = 0; it < 8; it++) {             // 128 rows x 16 uint4
            int idx = it * 256 + tid;
            int r = idx >> 4, ch = idx & 15;
            uint4 v = *(uint4*)(hs + r * CS + ch * 8);
            *(uint4*)((__nv_bfloat16*)C + (size_t)(row0 + r) * N + col0 + ch * 8) = v;
        }
    }
}

// -------- attention: mma.sync, warp-per-head, Q via direct LDG -------------
__global__ void __launch_bounds__(256)
attn_kernel(const __nv_bfloat16* __restrict__ qkv, const float* __restrict__ rpb,
            __nv_bfloat16* __restrict__ ow)
{
    extern __shared__ __align__(16) char asmem[];

    int w = threadIdx.x >> 5, lane = threadIdx.x & 31;
    int win = blockIdx.x;
    int g = lane >> 2, t = lane & 3;

    __nv_bfloat16* ksm = (__nv_bfloat16*)asmem + w * kWarpElems;
    __nv_bfloat16* vsm = ksm + 64 * kQRow;
    float* btab = (float*)(asmem + 8 * kWarpElems * 2) + w * 226;

    for (int i = lane; i < 225; i += 32) btab[i] = rpb[i * kNH + w];

    // stage K/V for this head: 64 rows x 32 bf16, row stride 40
    const __nv_bfloat16* gb = qkv + (size_t)win * 64 * 768 + w * 32;
    #pragma unroll
    for (int pass = 0; pass < 8; pass++) {
        int row = pass * 8 + (lane >> 2);
        int ch  = (lane & 3) * 8;
        const __nv_bfloat16* gq = gb + (size_t)row * 768 + ch;
        *(uint4*)(ksm + row * kQRow + ch) = *(const uint4*)(gq + 256);
        *(uint4*)(vsm + row * kQRow + ch) = *(const uint4*)(gq + 512);
    }
    __syncwarp();

    uint32_t kB = smem_u32(ksm), vB = smem_u32(vsm);
    int a_r = lane & 15, a_c = (lane >> 4) << 3;
    int t_r = (lane & 7) + ((lane >> 3) & 1) * 8, t_c = (lane >> 4) << 3;
    const float scale = 0.17677669529663687f;

    #pragma unroll
    for (int mt = 0; mt < 4; mt++) {
        int m0 = mt * 16;

        // Q fragments straight from global (A layout: rows g/g+8, cols 2t/2t+8)
        uint32_t qa[2][4];
        {
            const __nv_bfloat16* q0 = gb + (size_t)(m0 + g) * 768;
            const __nv_bfloat16* q8 = gb + (size_t)(m0 + g + 8) * 768;
            #pragma unroll
            for (int kc = 0; kc < 2; kc++) {
                int cb = kc * 16 + 2 * t;
                qa[kc][0] = *(const uint32_t*)(q0 + cb);
                qa[kc][1] = *(const uint32_t*)(q8 + cb);
                qa[kc][2] = *(const uint32_t*)(q0 + cb + 8);
                qa[kc][3] = *(const uint32_t*)(q8 + cb + 8);
            }
        }

        float sacc[8][4];
        #pragma unroll
        for (int nt = 0; nt < 8; nt++)
            #pragma unroll
            for (int e = 0; e < 4; e++) sacc[nt][e] = 0.f;

        #pragma unroll
        for (int kc = 0; kc < 2; kc++) {
            #pragma unroll
            for (int ng = 0; ng < 4; ng++) {
                uint32_t r0, r1, r2, r3;
                ldsm_x4(r0, r1, r2, r3,
                        kB + ((ng * 16 + a_r) * kQRow + kc * 16 + a_c) * 2);
                mma_bf16(sacc[2 * ng],     qa[kc][0], qa[kc][1], qa[kc][2], qa[kc][3], r0, r2);
                mma_bf16(sacc[2 * ng + 1], qa[kc][0], qa[kc][1], qa[kc][2], qa[kc][3], r1, r3);
            }
        }

        int ri0 = m0 + g, ri1 = ri0 + 8;
        int yi0 = ri0 >> 3, xi0 = ri0 & 7;
        int yi1 = ri1 >> 3, xi1 = ri1 & 7;
        float mx0 = -1e30f, mx1 = -1e30f;
        #pragma unroll
        for (int nt = 0; nt < 8; nt++) {
            #pragma unroll
            for (int c = 0; c < 2; c++) {
                int j = 8 * nt + 2 * t + c;
                int yj = j >> 3, xj = j & 7;
                float b0v = btab[(yi0 - yj + 7) * 15 + (xi0 - xj + 7)];
                float b1v = btab[(yi1 - yj + 7) * 15 + (xi1 - xj + 7)];
                sacc[nt][c]     = fmaf(sacc[nt][c],     scale, b0v);
                sacc[nt][c + 2] = fmaf(sacc[nt][c + 2], scale, b1v);
                mx0 = fmaxf(mx0, sacc[nt][c]);
                mx1 = fmaxf(mx1, sacc[nt][c + 2]);
            }
        }
        mx0 = fmaxf(mx0, __shfl_xor_sync(0xffffffffu, mx0, 1));
        mx0 = fmaxf(mx0, __shfl_xor_sync(0xffffffffu, mx0, 2));
        mx1 = fmaxf(mx1, __shfl_xor_sync(0xffffffffu, mx1, 1));
        mx1 = fmaxf(mx1, __shfl_xor_sync(0xffffffffu, mx1, 2));

        float sum0 = 0.f, sum1 = 0.f;
        #pragma unroll
        for (int nt = 0; nt < 8; nt++) {
            #pragma unroll
            for (int c = 0; c < 2; c++) {
                float p0 = __expf(sacc[nt][c]     - mx0);
                float p1 = __expf(sacc[nt][c + 2] - mx1);
                sacc[nt][c]     = p0;
                sacc[nt][c + 2] = p1;
                sum0 += p0;
                sum1 += p1;
            }
        }
        sum0 += __shfl_xor_sync(0xffffffffu, sum0, 1);
        sum0 += __shfl_xor_sync(0xffffffffu, sum0, 2);
        sum1 += __shfl_xor_sync(0xffffffffu, sum1, 1);
        sum1 += __shfl_xor_sync(0xffffffffu, sum1, 2);

        uint32_t pa[4][4];
        #pragma unroll
        for (int kcp = 0; kcp < 4; kcp++) {
            pa[kcp][0] = pack_bf16(sacc[2 * kcp][0],     sacc[2 * kcp][1]);
            pa[kcp][1] = pack_bf16(sacc[2 * kcp][2],     sacc[2 * kcp][3]);
            pa[kcp][2] = pack_bf16(sacc[2 * kcp + 1][0], sacc[2 * kcp + 1][1]);
            pa[kcp][3] = pack_bf16(sacc[2 * kcp + 1][2], sacc[2 * kcp + 1][3]);
        }

        float oacc[4][4];
        #pragma unroll
        for (int nt = 0; nt < 4; nt++)
            #pragma unroll
            for (int e = 0; e < 4; e++) oacc[nt][e] = 0.f;

        #pragma unroll
        for (int kcp = 0; kcp < 4; kcp++) {
            #pragma unroll
            for (int ng = 0; ng < 2; ng++) {
                uint32_t r0, r1, r2, r3;
                ldsm_x4_t(r0, r1, r2, r3,
                          vB + ((kcp * 16 + t_r) * kQRow + ng * 16 + t_c) * 2);
                mma_bf16(oacc[2 * ng],     pa[kcp][0], pa[kcp][1], pa[kcp][2], pa[kcp][3], r0, r1);
                mma_bf16(oacc[2 * ng + 1], pa[kcp][0], pa[kcp][1], pa[kcp][2], pa[kcp][3], r2, r3);
            }
        }

        float inv0 = 1.0f / sum0, inv1 = 1.0f / sum1;
        size_t ro0 = ((size_t)(win * 64 + ri0)) * kC + w * 32;
        size_t ro1 = ((size_t)(win * 64 + ri1)) * kC + w * 32;
        #pragma unroll
        for (int nt = 0; nt < 4; nt++) {
            int cc = nt * 8 + 2 * t;
            store2(ow, ro0 + cc, oacc[nt][0] * inv0, oacc[nt][1] * inv0);
            store2(ow, ro1 + cc, oacc[nt][2] * inv1, oacc[nt][3] * inv1);
        }
    }
}

// ------------------------------- launcher ----------------------------------
extern "C" void kernel_launch(void* const* d_in, const int* in_sizes, int n_in,
                              void* d_out, int out_size)
{
    const float* x      = (const float*)d_in[0];
    const float* cond   = (const float*)d_in[1];
    const float* gamma1 = (const float*)d_in[4];
    const float* beta1  = (const float*)d_in[5];
    const float* mod1_w = (const float*)d_in[6];
    const float* mod1_b = (const float*)d_in[7];
    const float* qkv_w  = (const float*)d_in[8];
    const float* qkv_b  = (const float*)d_in[9];
    const float* rpb    = (const float*)d_in[10];
    const float* proj_w = (const float*)d_in[11];
    const float* proj_b = (const float*)d_in[12];
    const float* gamma2 = (const float*)d_in[13];
    const float* beta2  = (const float*)d_in[14];
    const float* mod2_w = (const float*)d_in[15];
    const float* mod2_b = (const float*)d_in[16];
    const float* fc1_w  = (const float*)d_in[17];
    const float* fc1_b  = (const float*)d_in[18];
    const float* fc2_w  = (const float*)d_in[19];
    const float* fc2_b  = (const float*)d_in[20];
    float* out = (float*)d_out;

    void* pv;
    float *p_mod1, *p_mod2, *p_x2;
    __nv_bfloat16 *p_h, *p_qkv, *p_ow, *p_h2, *p_hid, *p_wb;
    cudaGetSymbolAddress(&pv, g_mod1); p_mod1 = (float*)pv;
    cudaGetSymbolAddress(&pv, g_mod2); p_mod2 = (float*)pv;
    cudaGetSymbolAddress(&pv, g_h);    p_h    = (__nv_bfloat16*)pv;
    cudaGetSymbolAddress(&pv, g_qkv);  p_qkv  = (__nv_bfloat16*)pv;
    cudaGetSymbolAddress(&pv, g_ow);   p_ow   = (__nv_bfloat16*)pv;
    cudaGetSymbolAddress(&pv, g_x2);   p_x2   = (float*)pv;
    cudaGetSymbolAddress(&pv, g_h2);   p_h2   = (__nv_bfloat16*)pv;
    cudaGetSymbolAddress(&pv, g_hid);  p_hid  = (__nv_bfloat16*)pv;
    cudaGetSymbolAddress(&pv, g_wb);   p_wb   = (__nv_bfloat16*)pv;

    __nv_bfloat16* qkvB  = p_wb;             // [256, 768]
    __nv_bfloat16* projB = p_wb + 196608;    // [256, 256]
    __nv_bfloat16* fc1B  = p_wb + 262144;    // [256, 1024]
    __nv_bfloat16* fc2B  = p_wb + 524288;    // [1024, 256]

    cudaFuncSetAttribute(gemm_tc<1, 0, __nv_bfloat16>,
                         cudaFuncAttributeMaxDynamicSharedMemorySize, kSmemBytes);
    cudaFuncSetAttribute(gemm_tc<2, 2, float>,
                         cudaFuncAttributeMaxDynamicSharedMemorySize, kSmemBytes);
    cudaFuncSetAttribute(gemm_tc<0, 1, __nv_bfloat16>,
                         cudaFuncAttributeMaxDynamicSharedMemorySize, kSmemBytes);
    cudaFuncSetAttribute(gemm_tc<0, 2, float>,
                         cudaFuncAttributeMaxDynamicSharedMemorySize, kSmemBytes);
    cudaFuncSetAttribute(attn_kernel,
                         cudaFuncAttributeMaxDynamicSharedMemorySize, kAttnSmem);

    // 1. prep: cond modulation + weight bf16 conversion (one launch)
    mod_kernel<<<dim3(kB, 2), 2 * kC>>>(cond, mod1_w, mod1_b, mod2_w, mod2_b);
    to_bf16_all<<<3072, 256>>>(qkv_w, proj_w, fc1_w, fc2_w, p_wb);

    // 2. adaLN #1 (fp32 -> bf16)
    adaln_kernel<<<kM / 32, 256>>>(x, p_mod1, gamma1, beta1, p_h);

    // 3. qkv GEMM (fused roll+partition gather)  M=65536 K=256 N=768 -> bf16
    gemm_tc<1, 0, __nv_bfloat16><<<dim3(kM / kBM, 6), 256, kSmemBytes>>>(
        p_h, qkvB, qkv_b, nullptr, p_qkv, kC, 3 * kC);

    // 4. windowed attention (tensor-core, warp-per-head)
    attn_kernel<<<kNWin, 256, kAttnSmem>>>(p_qkv, rpb, p_ow);

    // 5. proj GEMM (fused reverse gather + residual)  -> fp32 x2
    gemm_tc<2, 2, float><<<dim3(kM / kBM, 2), 256, kSmemBytes>>>(
        p_ow, projB, proj_b, x, p_x2, kC, kC);

    // 6. adaLN #2 (fp32 -> bf16)
    adaln_kernel<<<kM / 32, 256>>>(p_x2, p_mod2, gamma2, beta2, p_h2);

    // 7. fc1 GEMM + exact GELU  -> bf16 hid
    gemm_tc<0, 1, __nv_bfloat16><<<dim3(kM / kBM, 8), 256, kSmemBytes>>>(
        p_h2, fc1B, fc1_b, nullptr, p_hid, kC, kHid);

    // 8. fc2 GEMM + residual -> fp32 out
    gemm_tc<0, 2, float><<<dim3(kM / kBM, 2), 256, kSmemBytes>>>(
        p_hid, fc2B, fc2_b, p_x2, out, kHid, kC);
}

// round 15
// speedup vs baseline: 1.4906x; 1.4906x over previous
#include <cuda_runtime.h>
#include <cuda_bf16.h>
#include <cstdint>

// ---------------------------------------------------------------------------
// DiT Swin Transformer block — bf16 mma.sync everywhere (GEMMs + attention).
// GEMM: 256-thread CTAs, BM=128 BN=128 BK=64, cp.async x3, 2 CTAs/SM,
// smem-staged coalesced epilogue. Attention: warp-per-head mma.sync,
// Q fragments via direct LDG (2 CTAs/SM). adaLN: 4 rows/warp batched loads.
// B=16, H=W=64, L=4096, C=256, COND=128, HID=1024, NH=8, hd=32, WS=8, SHIFT=4
// ---------------------------------------------------------------------------

namespace {
constexpr int kB     = 16;
constexpr int kW     = 64;
constexpr int kL     = 64 * 64;        // 4096
constexpr int kC     = 256;
constexpr int kCond  = 128;
constexpr int kHid   = 1024;
constexpr int kNH    = 8;
constexpr int kN     = 64;             // tokens / window
constexpr int kShift = 4;
constexpr int kM     = kB * kL;        // 65536 rows
constexpr int kNWin  = kM / kN;        // 1024 windows

constexpr int kBM = 128, kBN = 128, kBK = 64;
constexpr int kAStr = kBK + 8;          // 72 bf16 = 144 B rows
constexpr int kBStr = kBN + 8;          // 136 bf16 = 272 B rows
constexpr int kABytes = kBM * kAStr * 2;            // 18432
constexpr int kBBytes = kBK * kBStr * 2;            // 17408
constexpr int kStage  = kABytes + kBBytes;          // 35840
constexpr int kStages = 3;
constexpr int kSmemBytes = kStages * kStage;        // 107520 (also > C-stage)

// attention smem: per-warp K/V [64][40] bf16 + per-head bias table
constexpr int kQRow      = 40;
constexpr int kWarpElems = 2 * 64 * kQRow;                       // 5120 bf16
constexpr int kAttnSmem  = 8 * kWarpElems * 2 + 8 * 226 * 4;     // 89152 B
}

// ------------------------------- scratch -----------------------------------
__device__ float g_mod1[kB * 2 * kC];
__device__ float g_mod2[kB * 2 * kC];
__device__ __align__(16) __nv_bfloat16 g_h  [(size_t)kM * kC];
__device__ __align__(16) __nv_bfloat16 g_qkv[(size_t)kM * 3 * kC];
__device__ __align__(16) __nv_bfloat16 g_ow [(size_t)kM * kC];
__device__ __align__(16) float         g_x2 [(size_t)kM * kC];
__device__ __align__(16) __nv_bfloat16 g_h2 [(size_t)kM * kC];
__device__ __align__(16) __nv_bfloat16 g_hid[(size_t)kM * kHid];
__device__ __align__(16) __nv_bfloat16 g_wb[786432];          // bf16 weights

// ---------------------------- helpers ---------------------------------------
__device__ __forceinline__ uint32_t smem_u32(const void* p) {
    uint32_t a;
    asm("{ .reg .u64 t; cvta.to.shared.u64 t, %1; cvt.u32.u64 %0, t; }"
        : "=r"(a) : "l"(p));
    return a;
}
__device__ __forceinline__ void ldsm_x4(uint32_t& r0, uint32_t& r1,
                                        uint32_t& r2, uint32_t& r3, uint32_t a) {
    asm volatile("ldmatrix.sync.aligned.m8n8.x4.shared.b16 {%0,%1,%2,%3}, [%4];"
                 : "=r"(r0), "=r"(r1), "=r"(r2), "=r"(r3) : "r"(a));
}
__device__ __forceinline__ void ldsm_x4_t(uint32_t& r0, uint32_t& r1,
                                          uint32_t& r2, uint32_t& r3, uint32_t a) {
    asm volatile("ldmatrix.sync.aligned.m8n8.x4.trans.shared.b16 {%0,%1,%2,%3}, [%4];"
                 : "=r"(r0), "=r"(r1), "=r"(r2), "=r"(r3) : "r"(a));
}
__device__ __forceinline__ void mma_bf16(float c[4], uint32_t a0, uint32_t a1,
                                         uint32_t a2, uint32_t a3,
                                         uint32_t b0, uint32_t b1) {
    asm volatile(
        "mma.sync.aligned.m16n8k16.row.col.f32.bf16.bf16.f32 "
        "{%0,%1,%2,%3}, {%4,%5,%6,%7}, {%8,%9}, {%0,%1,%2,%3};"
        : "+f"(c[0]), "+f"(c[1]), "+f"(c[2]), "+f"(c[3])
        : "r"(a0), "r"(a1), "r"(a2), "r"(a3), "r"(b0), "r"(b1));
}
__device__ __forceinline__ uint32_t pack_bf16(float x, float y) {
    __nv_bfloat162 v = __floats2bfloat162_rn(x, y);
    return *(uint32_t*)&v;
}
__device__ __forceinline__ void store2(float* C, size_t off, float a, float b) {
    float2 v = {a, b};
    *(float2*)(C + off) = v;
}
__device__ __forceinline__ void store2(__nv_bfloat16* C, size_t off, float a, float b) {
    *(uint32_t*)(C + off) = pack_bf16(a, b);
}

#define CP16(dst, src) \
    asm volatile("cp.async.cg.shared.global [%0], [%1], 16;" :: "r"(dst), "l"(src))
#define CP_COMMIT() asm volatile("cp.async.commit_group;")
#define CP_WAIT1()  asm volatile("cp.async.wait_group 1;")

// ------------------------- cond modulation GEMM ----------------------------
__global__ void mod_kernel(const float* __restrict__ cond,
                           const float* __restrict__ w1, const float* __restrict__ b1,
                           const float* __restrict__ w2, const float* __restrict__ b2)
{
    int b = blockIdx.x, which = blockIdx.y;
    const float* w  = which ? w2 : w1;
    const float* bb = which ? b2 : b1;
    float* out      = which ? g_mod2 : g_mod1;

    __shared__ float cs[kCond];
    int j = threadIdx.x;
    if (j < kCond) cs[j] = cond[b * kCond + j];
    __syncthreads();

    float s = bb[j];
    #pragma unroll 8
    for (int k = 0; k < kCond; k++) s = fmaf(cs[k], w[k * (2 * kC) + j], s);
    out[b * (2 * kC) + j] = s;
}

// ------------- adaLN: 4 rows per warp, batched loads (MLP=8) ---------------
__global__ void __launch_bounds__(256)
adaln_kernel(const float* __restrict__ x, const float* __restrict__ mod,
             const float* __restrict__ g,  const float* __restrict__ bt,
             __nv_bfloat16* __restrict__ out)
{
    int wid  = threadIdx.x >> 5, lane = threadIdx.x & 31;
    int row0 = blockIdx.x * 32 + wid * 4;
    int c0   = lane * 8;

    float4 v[4][2];
    #pragma unroll
    for (int r = 0; r < 4; r++) {
        const float* xr = x + (size_t)(row0 + r) * kC + c0;
        v[r][0] = *(const float4*)(xr);
        v[r][1] = *(const float4*)(xr + 4);
    }

    #pragma unroll
    for (int r = 0; r < 4; r++) {
        float s = v[r][0].x + v[r][0].y + v[r][0].z + v[r][0].w
                + v[r][1].x + v[r][1].y + v[r][1].z + v[r][1].w;
        #pragma unroll
        for (int o = 16; o > 0; o >>= 1) s += __shfl_xor_sync(0xffffffffu, s, o);
        float mu = s * (1.0f / kC);

        float d[8] = {v[r][0].x - mu, v[r][0].y - mu, v[r][0].z - mu, v[r][0].w - mu,
                      v[r][1].x - mu, v[r][1].y - mu, v[r][1].z - mu, v[r][1].w - mu};
        float vs = 0.f;
        #pragma unroll
        for (int e = 0; e < 8; e++) vs = fmaf(d[e], d[e], vs);
        #pragma unroll
        for (int o = 16; o > 0; o >>= 1) vs += __shfl_xor_sync(0xffffffffu, vs, o);
        float rsig = rsqrtf(vs * (1.0f / kC) + 1e-6f);

        int row = row0 + r;
        const float* mrow = mod + (row >> 12) * (2 * kC);
        uint4 pk;
        uint32_t* pw = (uint32_t*)&pk;
        #pragma unroll
        for (int e2 = 0; e2 < 4; e2++) {
            int c = c0 + 2 * e2;
            float dg0 = mrow[c],     db0 = mrow[kC + c];
            float dg1 = mrow[c + 1], db1 = mrow[kC + c + 1];
            float r0 = (g[c]     * (1.0f + dg0)) * (d[2 * e2]     * rsig) + (bt[c]     + db0);
            float r1 = (g[c + 1] * (1.0f + dg1)) * (d[2 * e2 + 1] * rsig) + (bt[c + 1] + db1);
            pw[e2] = pack_bf16(r0, r1);
        }
        *(uint4*)(out + (size_t)row * kC + c0) = pk;
    }
}

// ------------------- weights fp32 -> bf16 (single launch) -------------------
__global__ void to_bf16_all(const float* __restrict__ s0, const float* __restrict__ s1,
                            const float* __restrict__ s2, const float* __restrict__ s3,
                            __nv_bfloat16* __restrict__ dst)
{
    int i = blockIdx.x * 256 + threadIdx.x;          // 0 .. 786431
    const float* src;
    int off;
    if (i < 196608)      { src = s0; off = 0; }
    else if (i < 262144) { src = s1; off = 196608; }
    else if (i < 524288) { src = s2; off = 262144; }
    else                 { src = s3; off = 524288; }
    dst[i] = __float2bfloat16(src[i - off]);
}

// ----------------------------- row gathers ---------------------------------
template <int GATHER>
__device__ __forceinline__ int gather_row(int r)
{
    if (GATHER == 1) {
        int win = r >> 6, n = r & 63;
        int b = win >> 6, wrem = win & 63;
        int yr = ((wrem >> 3) << 3) + (n >> 3);
        int xr = ((wrem & 7) << 3) + (n & 7);
        int y = (yr + kShift) & 63;
        int x = (xr + kShift) & 63;
        return b * kL + y * kW + x;
    } else if (GATHER == 2) {
        int b = r >> 12, rem = r & 4095;
        int y = rem >> 6, x = rem & 63;
        int yr = (y - kShift) & 63;
        int xr = (x - kShift) & 63;
        int win = b * 64 + ((yr >> 3) << 3) + (xr >> 3);
        int n   = ((yr & 7) << 3) + (xr & 7);
        return win * kN + n;
    }
    return r;
}

// ------- bf16 mma GEMM: 256 threads, BK=64, cp.async x3, 2 CTAs/SM ---------
// Epilogue staged through smem -> fully coalesced 16B global stores.
template <int GATHER, int EPI, typename OutT>
__global__ void __launch_bounds__(256, 2)
gemm_tc(const __nv_bfloat16* __restrict__ A, const __nv_bfloat16* __restrict__ Bw,
        const float* __restrict__ bias, const float* __restrict__ res,
        OutT* __restrict__ C, int K, int N)
{
    extern __shared__ __align__(128) char smem[];

    int tid  = threadIdx.x;
    int wid  = tid >> 5, lane = tid & 31;
    int g    = lane >> 2, t = lane & 3;
    int wm   = wid & 3, wn = wid >> 2;
    int row0 = blockIdx.x * kBM;
    int col0 = blockIdx.y * kBN;

    int a_r = (lane & 15);
    int a_c = (lane >> 4) << 3;
    int b_r = (lane & 7) + ((lane >> 3) & 1) * 8;
    int b_c = (lane >> 4) << 3;

    int arowA[4];
    #pragma unroll
    for (int p = 0; p < 4; p++)
        arowA[p] = gather_row<GATHER>(row0 + ((p * 256 + tid) >> 3));

    float acc[2][8][4];
    #pragma unroll
    for (int mt = 0; mt < 2; mt++)
        #pragma unroll
        for (int nt = 0; nt < 8; nt++)
            #pragma unroll
            for (int e = 0; e < 4; e++) acc[mt][nt][e] = 0.f;

    int niter = K >> 6;

    auto load_stage = [&](int i, int slot) {
        int k0 = i << 6;
        char* As = smem + slot * kStage;
        char* Bs = As + kABytes;
        #pragma unroll
        for (int p = 0; p < 4; p++) {
            int idx = tid + p * 256;
            int r = idx >> 3, ch = idx & 7;
            uint32_t dst = smem_u32(As + r * (kAStr * 2) + ch * 16);
            CP16(dst, A + (size_t)arowA[p] * K + k0 + ch * 8);
        }
        #pragma unroll
        for (int p = 0; p < 4; p++) {
            int idx = tid + p * 256;
            int r = idx >> 4, ch = idx & 15;
            uint32_t dst = smem_u32(Bs + r * (kBStr * 2) + ch * 16);
            CP16(dst, Bw + (size_t)(k0 + r) * N + col0 + ch * 8);
        }
        CP_COMMIT();
    };

    load_stage(0, 0);
    load_stage(1, 1);

    for (int i = 0; i < niter; i++) {
        CP_WAIT1();
        __syncthreads();

        if (i + 2 < niter) load_stage(i + 2, (i + 2) % 3);
        else CP_COMMIT();

        uint32_t aB = smem_u32(smem + (i % 3) * kStage);
        uint32_t bB = aB + kABytes;

        #pragma unroll
        for (int ks = 0; ks < 4; ks++) {
            int k0 = ks * 16;
            uint32_t af[2][4];
            #pragma unroll
            for (int mt = 0; mt < 2; mt++) {
                uint32_t addr = aB + (wm * 32 + mt * 16 + a_r) * (kAStr * 2)
                                   + (k0 + a_c) * 2;
                ldsm_x4(af[mt][0], af[mt][1], af[mt][2], af[mt][3], addr);
            }
            uint32_t bf[8][2];
            #pragma unroll
            for (int n2 = 0; n2 < 4; n2++) {
                uint32_t addr = bB + (k0 + b_r) * (kBStr * 2)
                                   + (wn * 64 + n2 * 16 + b_c) * 2;
                uint32_t r0, r1, r2, r3;
                ldsm_x4_t(r0, r1, r2, r3, addr);
                bf[n2 * 2 + 0][0] = r0; bf[n2 * 2 + 0][1] = r1;
                bf[n2 * 2 + 1][0] = r2; bf[n2 * 2 + 1][1] = r3;
            }
            #pragma unroll
            for (int mt = 0; mt < 2; mt++)
                #pragma unroll
                for (int nt = 0; nt < 8; nt++)
                    mma_bf16(acc[mt][nt], af[mt][0], af[mt][1], af[mt][2], af[mt][3],
                             bf[nt][0], bf[nt][1]);
        }
    }

    // -------------------- staged epilogue (coalesced stores) ----------------
    __syncthreads();                       // mainloop done; stage smem is free

    if constexpr (sizeof(OutT) == 4) {
        constexpr int CS = 132;            // fp32 stage stride (528 B rows)
        float* cs = (float*)smem;
        #pragma unroll
        for (int mt = 0; mt < 2; mt++) {
            int r0 = wm * 32 + mt * 16 + g;
            #pragma unroll
            for (int nt = 0; nt < 8; nt++) {
                int cc = wn * 64 + nt * 8 + t * 2;
                float2 bv = *(const float2*)(bias + col0 + cc);
                float v0 = acc[mt][nt][0] + bv.x;
                float v1 = acc[mt][nt][1] + bv.y;
                float v2 = acc[mt][nt][2] + bv.x;
                float v3 = acc[mt][nt][3] + bv.y;
                if (EPI == 1) {
                    v0 = 0.5f * v0 * (1.0f + erff(v0 * 0.70710678118654752f));
                    v1 = 0.5f * v1 * (1.0f + erff(v1 * 0.70710678118654752f));
                    v2 = 0.5f * v2 * (1.0f + erff(v2 * 0.70710678118654752f));
                    v3 = 0.5f * v3 * (1.0f + erff(v3 * 0.70710678118654752f));
                }
                float2 o0 = {v0, v1}, o1 = {v2, v3};
                *(float2*)(cs + r0 * CS + cc)       = o0;
                *(float2*)(cs + (r0 + 8) * CS + cc) = o1;
            }
        }
        __syncthreads();
        #pragma unroll
        for (int it = 0; it < 16; it++) {            // 128 rows x 32 float4
            int idx = it * 256 + tid;
            int r = idx >> 5, ch = idx & 31;
            float4 v = *(float4*)(cs + r * CS + ch * 4);
            size_t go = (size_t)(row0 + r) * N + col0 + ch * 4;
            if (EPI == 2) {
                float4 q = *(const float4*)(res + go);
                v.x += q.x; v.y += q.y; v.z += q.z; v.w += q.w;
            }
            *(float4*)((float*)C + go) = v;
        }
    } else {
        constexpr int CS = 136;            // bf16 stage stride (272 B rows)
        __nv_bfloat16* hs = (__nv_bfloat16*)smem;
        #pragma unroll
        for (int mt = 0; mt < 2; mt++) {
            int r0 = wm * 32 + mt * 16 + g;
            #pragma unroll
            for (int nt = 0; nt < 8; nt++) {
                int cc = wn * 64 + nt * 8 + t * 2;
                float2 bv = *(const float2*)(bias + col0 + cc);
                float v0 = acc[mt][nt][0] + bv.x;
                float v1 = acc[mt][nt][1] + bv.y;
                float v2 = acc[mt][nt][2] + bv.x;
                float v3 = acc[mt][nt][3] + bv.y;
                if (EPI == 1) {
                    v0 = 0.5f * v0 * (1.0f + erff(v0 * 0.70710678118654752f));
                    v1 = 0.5f * v1 * (1.0f + erff(v1 * 0.70710678118654752f));
                    v2 = 0.5f * v2 * (1.0f + erff(v2 * 0.70710678118654752f));
                    v3 = 0.5f * v3 * (1.0f + erff(v3 * 0.70710678118654752f));
                }
                *(uint32_t*)(hs + r0 * CS + cc)       = pack_bf16(v0, v1);
                *(uint32_t*)(hs + (r0 + 8) * CS + cc) = pack_bf16(v2, v3);
            }
        }
        __syncthreads();
        #pragma unroll
        for (int it = 0; it < 8; it++) {             // 128 rows x 16 uint4
            int idx = it * 256 + tid;
            int r = idx >> 4, ch = idx & 15;
            uint4 v = *(uint4*)(hs + r * CS + ch * 8);
            *(uint4*)((__nv_bfloat16*)C + (size_t)(row0 + r) * N + col0 + ch * 8) = v;
        }
    }
}

// -------- attention: mma.sync, warp-per-head, Q via direct LDG -------------
__global__ void __launch_bounds__(256)
attn_kernel(const __nv_bfloat16* __restrict__ qkv, const float* __restrict__ rpb,
            __nv_bfloat16* __restrict__ ow)
{
    extern __shared__ __align__(16) char asmem[];

    int w = threadIdx.x >> 5, lane = threadIdx.x & 31;
    int win = blockIdx.x;
    int g = lane >> 2, t = lane & 3;

    __nv_bfloat16* ksm = (__nv_bfloat16*)asmem + w * kWarpElems;
    __nv_bfloat16* vsm = ksm + 64 * kQRow;
    float* btab = (float*)(asmem + 8 * kWarpElems * 2) + w * 226;

    for (int i = lane; i < 225; i += 32) btab[i] = rpb[i * kNH + w];

    // stage K/V for this head: 64 rows x 32 bf16, row stride 40
    const __nv_bfloat16* gb = qkv + (size_t)win * 64 * 768 + w * 32;
    #pragma unroll
    for (int pass = 0; pass < 8; pass++) {
        int row = pass * 8 + (lane >> 2);
        int ch  = (lane & 3) * 8;
        const __nv_bfloat16* gq = gb + (size_t)row * 768 + ch;
        *(uint4*)(ksm + row * kQRow + ch) = *(const uint4*)(gq + 256);
        *(uint4*)(vsm + row * kQRow + ch) = *(const uint4*)(gq + 512);
    }
    __syncwarp();

    uint32_t kB = smem_u32(ksm), vB = smem_u32(vsm);
    int a_r = lane & 15, a_c = (lane >> 4) << 3;
    int t_r = (lane & 7) + ((lane >> 3) & 1) * 8, t_c = (lane >> 4) << 3;
    const float scale = 0.17677669529663687f;

    #pragma unroll
    for (int mt = 0; mt < 4; mt++) {
        int m0 = mt * 16;

        // Q fragments straight from global (A layout: rows g/g+8, cols 2t/2t+8)
        uint32_t qa[2][4];
        {
            const __nv_bfloat16* q0 = gb + (size_t)(m0 + g) * 768;
            const __nv_bfloat16* q8 = gb + (size_t)(m0 + g + 8) * 768;
            #pragma unroll
            for (int kc = 0; kc < 2; kc++) {
                int cb = kc * 16 + 2 * t;
                qa[kc][0] = *(const uint32_t*)(q0 + cb);
                qa[kc][1] = *(const uint32_t*)(q8 + cb);
                qa[kc][2] = *(const uint32_t*)(q0 + cb + 8);
                qa[kc][3] = *(const uint32_t*)(q8 + cb + 8);
            }
        }

        float sacc[8][4];
        #pragma unroll
        for (int nt = 0; nt < 8; nt++)
            #pragma unroll
            for (int e = 0; e < 4; e++) sacc[nt][e] = 0.f;

        #pragma unroll
        for (int kc = 0; kc < 2; kc++) {
            #pragma unroll
            for (int ng = 0; ng < 4; ng++) {
                uint32_t r0, r1, r2, r3;
                ldsm_x4(r0, r1, r2, r3,
                        kB + ((ng * 16 + a_r) * kQRow + kc * 16 + a_c) * 2);
                mma_bf16(sacc[2 * ng],     qa[kc][0], qa[kc][1], qa[kc][2], qa[kc][3], r0, r2);
                mma_bf16(sacc[2 * ng + 1], qa[kc][0], qa[kc][1], qa[kc][2], qa[kc][3], r1, r3);
            }
        }

        int ri0 = m0 + g, ri1 = ri0 + 8;
        int yi0 = ri0 >> 3, xi0 = ri0 & 7;
        int yi1 = ri1 >> 3, xi1 = ri1 & 7;
        float mx0 = -1e30f, mx1 = -1e30f;
        #pragma unroll
        for (int nt = 0; nt < 8; nt++) {
            #pragma unroll
            for (int c = 0; c < 2; c++) {
                int j = 8 * nt + 2 * t + c;
                int yj = j >> 3, xj = j & 7;
                float b0v = btab[(yi0 - yj + 7) * 15 + (xi0 - xj + 7)];
                float b1v = btab[(yi1 - yj + 7) * 15 + (xi1 - xj + 7)];
                sacc[nt][c]     = fmaf(sacc[nt][c],     scale, b0v);
                sacc[nt][c + 2] = fmaf(sacc[nt][c + 2], scale, b1v);
                mx0 = fmaxf(mx0, sacc[nt][c]);
                mx1 = fmaxf(mx1, sacc[nt][c + 2]);
            }
        }
        mx0 = fmaxf(mx0, __shfl_xor_sync(0xffffffffu, mx0, 1));
        mx0 = fmaxf(mx0, __shfl_xor_sync(0xffffffffu, mx0, 2));
        mx1 = fmaxf(mx1, __shfl_xor_sync(0xffffffffu, mx1, 1));
        mx1 = fmaxf(mx1, __shfl_xor_sync(0xffffffffu, mx1, 2));

        float sum0 = 0.f, sum1 = 0.f;
        #pragma unroll
        for (int nt = 0; nt < 8; nt++) {
            #pragma unroll
            for (int c = 0; c < 2; c++) {
                float p0 = __expf(sacc[nt][c]     - mx0);
                float p1 = __expf(sacc[nt][c + 2] - mx1);
                sacc[nt][c]     = p0;
                sacc[nt][c + 2] = p1;
                sum0 += p0;
                sum1 += p1;
            }
        }
        sum0 += __shfl_xor_sync(0xffffffffu, sum0, 1);
        sum0 += __shfl_xor_sync(0xffffffffu, sum0, 2);
        sum1 += __shfl_xor_sync(0xffffffffu, sum1, 1);
        sum1 += __shfl_xor_sync(0xffffffffu, sum1, 2);

        uint32_t pa[4][4];
        #pragma unroll
        for (int kcp = 0; kcp < 4; kcp++) {
            pa[kcp][0] = pack_bf16(sacc[2 * kcp][0],     sacc[2 * kcp][1]);
            pa[kcp][1] = pack_bf16(sacc[2 * kcp][2],     sacc[2 * kcp][3]);
            pa[kcp][2] = pack_bf16(sacc[2 * kcp + 1][0], sacc[2 * kcp + 1][1]);
            pa[kcp][3] = pack_bf16(sacc[2 * kcp + 1][2], sacc[2 * kcp + 1][3]);
        }

        float oacc[4][4];
        #pragma unroll
        for (int nt = 0; nt < 4; nt++)
            #pragma unroll
            for (int e = 0; e < 4; e++) oacc[nt][e] = 0.f;

        #pragma unroll
        for (int kcp = 0; kcp < 4; kcp++) {
            #pragma unroll
            for (int ng = 0; ng < 2; ng++) {
                uint32_t r0, r1, r2, r3;
                ldsm_x4_t(r0, r1, r2, r3,
                          vB + ((kcp * 16 + t_r) * kQRow + ng * 16 + t_c) * 2);
                mma_bf16(oacc[2 * ng],     pa[kcp][0], pa[kcp][1], pa[kcp][2], pa[kcp][3], r0, r1);
                mma_bf16(oacc[2 * ng + 1], pa[kcp][0], pa[kcp][1], pa[kcp][2], pa[kcp][3], r2, r3);
            }
        }

        float inv0 = 1.0f / sum0, inv1 = 1.0f / sum1;
        size_t ro0 = ((size_t)(win * 64 + ri0)) * kC + w * 32;
        size_t ro1 = ((size_t)(win * 64 + ri1)) * kC + w * 32;
        #pragma unroll
        for (int nt = 0; nt < 4; nt++) {
            int cc = nt * 8 + 2 * t;
            store2(ow, ro0 + cc, oacc[nt][0] * inv0, oacc[nt][1] * inv0);
            store2(ow, ro1 + cc, oacc[nt][2] * inv1, oacc[nt][3] * inv1);
        }
    }
}

// ------------------------------- launcher ----------------------------------
extern "C" void kernel_launch(void* const* d_in, const int* in_sizes, int n_in,
                              void* d_out, int out_size)
{
    const float* x      = (const float*)d_in[0];
    const float* cond   = (const float*)d_in[1];
    const float* gamma1 = (const float*)d_in[4];
    const float* beta1  = (const float*)d_in[5];
    const float* mod1_w = (const float*)d_in[6];
    const float* mod1_b = (const float*)d_in[7];
    const float* qkv_w  = (const float*)d_in[8];
    const float* qkv_b  = (const float*)d_in[9];
    const float* rpb    = (const float*)d_in[10];
    const float* proj_w = (const float*)d_in[11];
    const float* proj_b = (const float*)d_in[12];
    const float* gamma2 = (const float*)d_in[13];
    const float* beta2  = (const float*)d_in[14];
    const float* mod2_w = (const float*)d_in[15];
    const float* mod2_b = (const float*)d_in[16];
    const float* fc1_w  = (const float*)d_in[17];
    const float* fc1_b  = (const float*)d_in[18];
    const float* fc2_w  = (const float*)d_in[19];
    const float* fc2_b  = (const float*)d_in[20];
    float* out = (float*)d_out;

    void* pv;
    float *p_mod1, *p_mod2, *p_x2;
    __nv_bfloat16 *p_h, *p_qkv, *p_ow, *p_h2, *p_hid, *p_wb;
    cudaGetSymbolAddress(&pv, g_mod1); p_mod1 = (float*)pv;
    cudaGetSymbolAddress(&pv, g_mod2); p_mod2 = (float*)pv;
    cudaGetSymbolAddress(&pv, g_h);    p_h    = (__nv_bfloat16*)pv;
    cudaGetSymbolAddress(&pv, g_qkv);  p_qkv  = (__nv_bfloat16*)pv;
    cudaGetSymbolAddress(&pv, g_ow);   p_ow   = (__nv_bfloat16*)pv;
    cudaGetSymbolAddress(&pv, g_x2);   p_x2   = (float*)pv;
    cudaGetSymbolAddress(&pv, g_h2);   p_h2   = (__nv_bfloat16*)pv;
    cudaGetSymbolAddress(&pv, g_hid);  p_hid  = (__nv_bfloat16*)pv;
    cudaGetSymbolAddress(&pv, g_wb);   p_wb   = (__nv_bfloat16*)pv;

    __nv_bfloat16* qkvB  = p_wb;             // [256, 768]
    __nv_bfloat16* projB = p_wb + 196608;    // [256, 256]
    __nv_bfloat16* fc1B  = p_wb + 262144;    // [256, 1024]
    __nv_bfloat16* fc2B  = p_wb + 524288;    // [1024, 256]

    cudaFuncSetAttribute(gemm_tc<1, 0, __nv_bfloat16>,
                         cudaFuncAttributeMaxDynamicSharedMemorySize, kSmemBytes);
    cudaFuncSetAttribute(gemm_tc<2, 2, float>,
                         cudaFuncAttributeMaxDynamicSharedMemorySize, kSmemBytes);
    cudaFuncSetAttribute(gemm_tc<0, 1, __nv_bfloat16>,
                         cudaFuncAttributeMaxDynamicSharedMemorySize, kSmemBytes);
    cudaFuncSetAttribute(gemm_tc<0, 2, float>,
                         cudaFuncAttributeMaxDynamicSharedMemorySize, kSmemBytes);
    cudaFuncSetAttribute(attn_kernel,
                         cudaFuncAttributeMaxDynamicSharedMemorySize, kAttnSmem);

    // 1. prep: cond modulation + weight bf16 conversion (one launch)
    mod_kernel<<<dim3(kB, 2), 2 * kC>>>(cond, mod1_w, mod1_b, mod2_w, mod2_b);
    to_bf16_all<<<3072, 256>>>(qkv_w, proj_w, fc1_w, fc2_w, p_wb);

    // 2. adaLN #1 (fp32 -> bf16)
    adaln_kernel<<<kM / 32, 256>>>(x, p_mod1, gamma1, beta1, p_h);

    // 3. qkv GEMM (fused roll+partition gather)  M=65536 K=256 N=768 -> bf16
    gemm_tc<1, 0, __nv_bfloat16><<<dim3(kM / kBM, 6), 256, kSmemBytes>>>(
        p_h, qkvB, qkv_b, nullptr, p_qkv, kC, 3 * kC);

    // 4. windowed attention (tensor-core, warp-per-head)
    attn_kernel<<<kNWin, 256, kAttnSmem>>>(p_qkv, rpb, p_ow);

    // 5. proj GEMM (fused reverse gather + residual)  -> fp32 x2
    gemm_tc<2, 2, float><<<dim3(kM / kBM, 2), 256, kSmemBytes>>>(
        p_ow, projB, proj_b, x, p_x2, kC, kC);

    // 6. adaLN #2 (fp32 -> bf16)
    adaln_kernel<<<kM / 32, 256>>>(p_x2, p_mod2, gamma2, beta2, p_h2);

    // 7. fc1 GEMM + exact GELU  -> bf16 hid
    gemm_tc<0, 1, __nv_bfloat16><<<dim3(kM / kBM, 8), 256, kSmemBytes>>>(
        p_h2, fc1B, fc1_b, nullptr, p_hid, kC, kHid);

    // 8. fc2 GEMM + residual -> fp32 out
    gemm_tc<0, 2, float><<<dim3(kM / kBM, 2), 256, kSmemBytes>>>(
        p_hid, fc2B, fc2_b, p_x2, out, kHid, kC);
}